// round 3
// baseline (speedup 1.0000x reference)
#include <cuda_runtime.h>
#include <math.h>

// Problem constants (shapes from reference setup_inputs)
#define D        256
#define NSPLIT   18
#define BM       128
#define BN       128
#define BK       16
#define NKCHUNK  (D / BK)     // 16
#define BM2      64
#define BN2      64

// Static device scratch (no allocation allowed)
__device__ float g_pmax[4096 * NSPLIT];
__device__ int   g_pidx[4096 * NSPLIT];
__device__ int   g_nn[4096];
__device__ float g_logits[2u * 2048u * 2048u];   // 32 MB
__device__ float g_rowterm[4096];

// ---- packed fp32x2 helpers (FFMA2 is PTX-only; ptxas won't emit from C++) ----
static __device__ __forceinline__ void fma2(unsigned long long& d,
                                            unsigned long long a,
                                            unsigned long long b) {
    asm("fma.rn.f32x2 %0, %1, %2, %0;" : "+l"(d) : "l"(a), "l"(b));
}
static __device__ __forceinline__ float lo32(unsigned long long v) {
    return __int_as_float((int)(unsigned)(v & 0xffffffffull));
}
static __device__ __forceinline__ float hi32(unsigned long long v) {
    return __int_as_float((int)(unsigned)(v >> 32));
}

// ============================================================================
// Stage 1: sim = emb @ queue^T with fully-fused running argmax.
// Grid (B/BM, NSPLIT); block 256 threads, 8x8 per-thread tile, f32x2 FMA,
// double-buffered smem (1 sync per k-chunk), argmax carried in registers.
// ============================================================================
__global__ __launch_bounds__(256, 2)
void argmax_kernel(const float* __restrict__ emb, const float* __restrict__ queue,
                   int B, int Q)
{
    // A duplicated as {a,a} pairs so FFMA2 needs no packing movs.
    __shared__ float2 As2[2][BK][BM];     // 32 KB
    __shared__ float  Bs [2][BK][BN];     // 16 KB   (total 48 KB exactly)

    const int tid = threadIdx.x;
    const int tx  = tid & 15;            // cols tx*8 .. tx*8+7
    const int ty  = tid >> 4;            // rows ty*8 .. ty*8+7
    const int m0  = blockIdx.x * BM;
    const int NCHUNKS = Q / BN;          // 512

    const int lrow = tid >> 1;           // 0..127
    const int lk   = (tid & 1) * 8;      // 0 or 8

    const float* arow = emb + (size_t)(m0 + lrow) * D + lk;

    // per-thread running argmax over this thread's 8 rows
    float bval[8];
    int   bidx[8];
    #pragma unroll
    for (int i = 0; i < 8; i++) { bval[i] = -INFINITY; bidx[i] = 0x7fffffff; }

    for (int c = blockIdx.y; c < NCHUNKS; c += NSPLIT) {
        const int n0 = c * BN;
        const float* brow = queue + (size_t)(n0 + lrow) * D + lk;

        unsigned long long acc[8][4];
        #pragma unroll
        for (int i = 0; i < 8; i++)
            #pragma unroll
            for (int j = 0; j < 4; j++) acc[i][j] = 0ull;

        // ---- prime: load + store chunk 0 into buffer 0 ----
        {
            float4 a0 = *(const float4*)(arow + 0);
            float4 a1 = *(const float4*)(arow + 4);
            float4 b0 = *(const float4*)(brow + 0);
            float4 b1 = *(const float4*)(brow + 4);
            As2[0][lk + 0][lrow] = make_float2(a0.x, a0.x);
            As2[0][lk + 1][lrow] = make_float2(a0.y, a0.y);
            As2[0][lk + 2][lrow] = make_float2(a0.z, a0.z);
            As2[0][lk + 3][lrow] = make_float2(a0.w, a0.w);
            As2[0][lk + 4][lrow] = make_float2(a1.x, a1.x);
            As2[0][lk + 5][lrow] = make_float2(a1.y, a1.y);
            As2[0][lk + 6][lrow] = make_float2(a1.z, a1.z);
            As2[0][lk + 7][lrow] = make_float2(a1.w, a1.w);
            Bs[0][lk + 0][lrow] = b0.x;  Bs[0][lk + 1][lrow] = b0.y;
            Bs[0][lk + 2][lrow] = b0.z;  Bs[0][lk + 3][lrow] = b0.w;
            Bs[0][lk + 4][lrow] = b1.x;  Bs[0][lk + 5][lrow] = b1.y;
            Bs[0][lk + 6][lrow] = b1.z;  Bs[0][lk + 7][lrow] = b1.w;
        }

        #pragma unroll 1
        for (int kc = 0; kc < NKCHUNK; kc++) {
            __syncthreads();
            const int cur = kc & 1;
            const bool more = (kc + 1 < NKCHUNK);
            float4 a0, a1, b0, b1;
            if (more) {                       // prefetch next chunk (hidden by compute)
                const int ko = (kc + 1) * BK;
                a0 = *(const float4*)(arow + ko + 0);
                a1 = *(const float4*)(arow + ko + 4);
                b0 = *(const float4*)(brow + ko + 0);
                b1 = *(const float4*)(brow + ko + 4);
            }
            #pragma unroll
            for (int k = 0; k < BK; k++) {
                ulonglong2 a01 = *(const ulonglong2*)&As2[cur][k][ty * 8 + 0];
                ulonglong2 a23 = *(const ulonglong2*)&As2[cur][k][ty * 8 + 2];
                ulonglong2 a45 = *(const ulonglong2*)&As2[cur][k][ty * 8 + 4];
                ulonglong2 a67 = *(const ulonglong2*)&As2[cur][k][ty * 8 + 6];
                ulonglong2 bv0 = *(const ulonglong2*)&Bs[cur][k][tx * 8 + 0];
                ulonglong2 bv1 = *(const ulonglong2*)&Bs[cur][k][tx * 8 + 4];
                fma2(acc[0][0], a01.x, bv0.x); fma2(acc[0][1], a01.x, bv0.y);
                fma2(acc[0][2], a01.x, bv1.x); fma2(acc[0][3], a01.x, bv1.y);
                fma2(acc[1][0], a01.y, bv0.x); fma2(acc[1][1], a01.y, bv0.y);
                fma2(acc[1][2], a01.y, bv1.x); fma2(acc[1][3], a01.y, bv1.y);
                fma2(acc[2][0], a23.x, bv0.x); fma2(acc[2][1], a23.x, bv0.y);
                fma2(acc[2][2], a23.x, bv1.x); fma2(acc[2][3], a23.x, bv1.y);
                fma2(acc[3][0], a23.y, bv0.x); fma2(acc[3][1], a23.y, bv0.y);
                fma2(acc[3][2], a23.y, bv1.x); fma2(acc[3][3], a23.y, bv1.y);
                fma2(acc[4][0], a45.x, bv0.x); fma2(acc[4][1], a45.x, bv0.y);
                fma2(acc[4][2], a45.x, bv1.x); fma2(acc[4][3], a45.x, bv1.y);
                fma2(acc[5][0], a45.y, bv0.x); fma2(acc[5][1], a45.y, bv0.y);
                fma2(acc[5][2], a45.y, bv1.x); fma2(acc[5][3], a45.y, bv1.y);
                fma2(acc[6][0], a67.x, bv0.x); fma2(acc[6][1], a67.x, bv0.y);
                fma2(acc[6][2], a67.x, bv1.x); fma2(acc[6][3], a67.x, bv1.y);
                fma2(acc[7][0], a67.y, bv0.x); fma2(acc[7][1], a67.y, bv0.y);
                fma2(acc[7][2], a67.y, bv1.x); fma2(acc[7][3], a67.y, bv1.y);
            }
            if (more) {
                const int nb = cur ^ 1;
                As2[nb][lk + 0][lrow] = make_float2(a0.x, a0.x);
                As2[nb][lk + 1][lrow] = make_float2(a0.y, a0.y);
                As2[nb][lk + 2][lrow] = make_float2(a0.z, a0.z);
                As2[nb][lk + 3][lrow] = make_float2(a0.w, a0.w);
                As2[nb][lk + 4][lrow] = make_float2(a1.x, a1.x);
                As2[nb][lk + 5][lrow] = make_float2(a1.y, a1.y);
                As2[nb][lk + 6][lrow] = make_float2(a1.z, a1.z);
                As2[nb][lk + 7][lrow] = make_float2(a1.w, a1.w);
                Bs[nb][lk + 0][lrow] = b0.x;  Bs[nb][lk + 1][lrow] = b0.y;
                Bs[nb][lk + 2][lrow] = b0.z;  Bs[nb][lk + 3][lrow] = b0.w;
                Bs[nb][lk + 4][lrow] = b1.x;  Bs[nb][lk + 5][lrow] = b1.y;
                Bs[nb][lk + 6][lrow] = b1.z;  Bs[nb][lk + 7][lrow] = b1.w;
            }
        }

        // register-resident argmax update (cols ascend => strict > keeps first)
        #pragma unroll
        for (int i = 0; i < 8; i++) {
            #pragma unroll
            for (int j = 0; j < 4; j++) {
                const int c0 = n0 + tx * 8 + j * 2;
                const float v0 = lo32(acc[i][j]);
                const float v1 = hi32(acc[i][j]);
                if (v0 > bval[i]) { bval[i] = v0; bidx[i] = c0; }
                if (v1 > bval[i]) { bval[i] = v1; bidx[i] = c0 + 1; }
            }
        }
    }

    // cross-tx reduction via shuffles (lanes 0-15 / 16-31 reduce independently)
    #pragma unroll
    for (int i = 0; i < 8; i++) {
        float v = bval[i]; int id = bidx[i];
        #pragma unroll
        for (int o = 8; o; o >>= 1) {
            float ov = __shfl_xor_sync(0xffffffffu, v, o);
            int   oi = __shfl_xor_sync(0xffffffffu, id, o);
            if (ov > v || (ov == v && oi < id)) { v = ov; id = oi; }
        }
        if (tx == 0) {
            g_pmax[(size_t)(m0 + ty * 8 + i) * NSPLIT + blockIdx.y] = v;
            g_pidx[(size_t)(m0 + ty * 8 + i) * NSPLIT + blockIdx.y] = id;
        }
    }
}

// Merge the NSPLIT partial argmaxes per row (idx tie-break => first occurrence,
// matching jnp.argmax).
__global__ void merge_argmax_kernel(int B)
{
    int i = blockIdx.x * blockDim.x + threadIdx.x;
    if (i >= B) return;
    float bv = -INFINITY; int bi = 0x7fffffff;
    #pragma unroll
    for (int s = 0; s < NSPLIT; s++) {
        float v = g_pmax[(size_t)i * NSPLIT + s];
        int  id = g_pidx[(size_t)i * NSPLIT + s];
        if (v > bv || (v == bv && id < bi)) { bv = v; bi = id; }
    }
    g_nn[i] = bi;
}

// ============================================================================
// Stage 2a: logits[s][i][j] = 10 * dot(queue[nn[s*half+i]], preds[(1-s)*half+j])
// 64x64 block tile, 4x4 per-thread tile.
// ============================================================================
__global__ __launch_bounds__(256)
void logits_kernel(const float* __restrict__ queue, const float* __restrict__ preds,
                   int half)
{
    __shared__ int   idx_s[BM2];
    __shared__ float As[BK][BM2 + 4];
    __shared__ float Bs[BK][BN2 + 4];

    const int tid = threadIdx.x;
    const int tx = tid & 15;    // cols tx*4..+3
    const int ty = tid >> 4;    // rows ty*4..+3
    const int s  = blockIdx.z;
    const int m0 = blockIdx.x * BM2;
    const int n0 = blockIdx.y * BN2;

    if (tid < BM2) idx_s[tid] = g_nn[s * half + m0 + tid];
    __syncthreads();

    const float* pb = preds + (size_t)(1 - s) * half * D;

    const int lm  = tid >> 2;        // 0..63
    const int lk4 = (tid & 3) * 4;   // 0,4,8,12

    float acc[4][4] = {};

    for (int k0 = 0; k0 < D; k0 += BK) {
        float4 av = *(const float4*)&queue[(size_t)idx_s[lm] * D + k0 + lk4];
        float4 bv = *(const float4*)&pb[(size_t)(n0 + lm) * D + k0 + lk4];
        __syncthreads();
        As[lk4 + 0][lm] = av.x; As[lk4 + 1][lm] = av.y;
        As[lk4 + 2][lm] = av.z; As[lk4 + 3][lm] = av.w;
        Bs[lk4 + 0][lm] = bv.x; Bs[lk4 + 1][lm] = bv.y;
        Bs[lk4 + 2][lm] = bv.z; Bs[lk4 + 3][lm] = bv.w;
        __syncthreads();
        #pragma unroll
        for (int k = 0; k < BK; k++) {
            float4 a = *(const float4*)&As[k][ty * 4];
            float4 b = *(const float4*)&Bs[k][tx * 4];
            float am[4] = {a.x, a.y, a.z, a.w};
            float bn[4] = {b.x, b.y, b.z, b.w};
            #pragma unroll
            for (int i = 0; i < 4; i++)
                #pragma unroll
                for (int j = 0; j < 4; j++)
                    acc[i][j] += am[i] * bn[j];
        }
    }

    #pragma unroll
    for (int i = 0; i < 4; i++) {
        const int row = s * half + m0 + ty * 4 + i;
        float4 o = make_float4(acc[i][0] * 10.f, acc[i][1] * 10.f,
                               acc[i][2] * 10.f, acc[i][3] * 10.f);
        *(float4*)&g_logits[(size_t)row * half + n0 + tx * 4] = o;
    }
}

// ============================================================================
// Stage 2b: per-row  logsumexp(row) - row[diag]   (deterministic reductions)
// ============================================================================
__global__ __launch_bounds__(256)
void ce_row_kernel(int half)
{
    __shared__ float red[8];
    const int row = blockIdx.x;
    const int tid = threadIdx.x;
    const float* L = g_logits + (size_t)row * half;

    float m = -INFINITY;
    for (int j = tid; j < half; j += 256) m = fmaxf(m, L[j]);
    #pragma unroll
    for (int o = 16; o; o >>= 1) m = fmaxf(m, __shfl_xor_sync(0xffffffffu, m, o));
    if ((tid & 31) == 0) red[tid >> 5] = m;
    __syncthreads();
    if (tid == 0) {
        float t = red[0];
        #pragma unroll
        for (int w = 1; w < 8; w++) t = fmaxf(t, red[w]);
        red[0] = t;
    }
    __syncthreads();
    const float bm = red[0];
    __syncthreads();

    float sum = 0.f;
    for (int j = tid; j < half; j += 256) sum += expf(L[j] - bm);
    #pragma unroll
    for (int o = 16; o; o >>= 1) sum += __shfl_xor_sync(0xffffffffu, sum, o);
    if ((tid & 31) == 0) red[tid >> 5] = sum;
    __syncthreads();
    if (tid == 0) {
        float t = 0.f;
        #pragma unroll
        for (int w = 0; w < 8; w++) t += red[w];
        int diag = row % half;     // labels = arange(half)
        g_rowterm[row] = logf(t) + bm - L[diag];
    }
}

// loss = (mean_ab + mean_ba)/2 = sum(rowterm) / (2*half*2)
__global__ __launch_bounds__(256)
void final_kernel(float* __restrict__ out, int total)
{
    __shared__ float red[8];
    const int tid = threadIdx.x;
    float s = 0.f;
    for (int i = tid; i < total; i += 256) s += g_rowterm[i];
    #pragma unroll
    for (int o = 16; o; o >>= 1) s += __shfl_xor_sync(0xffffffffu, s, o);
    if ((tid & 31) == 0) red[tid >> 5] = s;
    __syncthreads();
    if (tid == 0) {
        float t = 0.f;
        #pragma unroll
        for (int w = 0; w < 8; w++) t += red[w];
        out[0] = t / (float)total;
    }
}

// ============================================================================
extern "C" void kernel_launch(void* const* d_in, const int* in_sizes, int n_in,
                              void* d_out, int out_size)
{
    const float* emb   = (const float*)d_in[0];   // [B, D]
    const float* preds = (const float*)d_in[1];   // [B, D]
    const float* queue = (const float*)d_in[2];   // [Q, D], rows unit-norm

    const int B = in_sizes[0] / D;     // 4096
    const int Q = in_sizes[2] / D;     // 65536
    const int half = B / 2;            // 2048

    argmax_kernel<<<dim3(B / BM, NSPLIT), 256>>>(emb, queue, B, Q);
    merge_argmax_kernel<<<(B + 255) / 256, 256>>>(B);
    logits_kernel<<<dim3(half / BM2, half / BN2, 2), 256>>>(queue, preds, half);
    ce_row_kernel<<<2 * half, 256>>>(half);
    final_kernel<<<1, 256>>>((float*)d_out, 2 * half);
}

// round 5
// speedup vs baseline: 1.2271x; 1.2271x over previous
#include <cuda_runtime.h>
#include <cuda_bf16.h>
#include <math.h>
#include <cstdint>

// ---------------- problem constants ----------------
#define D        256
#define NSPLIT   18
#define NTILES   512          // Q / 128
#define NCHUNK   24           // 3 split terms x (256/32)
#define BM2      64
#define BN2      64
#define BK2      16

// ---------------- static device scratch ----------------
__device__ __align__(16) __nv_bfloat16 g_emb_hi[4096 * 256];
__device__ __align__(16) __nv_bfloat16 g_emb_lo[4096 * 256];
__device__ __align__(16) __nv_bfloat16 g_q_hi[65536 * 256];
__device__ __align__(16) __nv_bfloat16 g_q_lo[65536 * 256];
__device__ float g_pmax[4096 * NSPLIT];
__device__ int   g_pidx[4096 * NSPLIT];
__device__ int   g_nn[4096];
__device__ float g_logits[2u * 2048u * 2048u];
__device__ float g_rowterm[4096];

// ---------------- PTX helpers (plain sm_103-safe: sm_80+ features only) ----
static __device__ __forceinline__ uint32_t smem_to_u32(const void* p) {
    uint32_t a;
    asm("{ .reg .u64 t; cvta.to.shared.u64 t, %1; cvt.u32.u64 %0, t; }"
        : "=r"(a) : "l"(p));
    return a;
}
static __device__ __forceinline__ void cp16(uint32_t dst, const void* src) {
    asm volatile("cp.async.cg.shared.global [%0], [%1], 16;"
                 :: "r"(dst), "l"(src) : "memory");
}
#define CP_COMMIT() asm volatile("cp.async.commit_group;" ::: "memory")
#define CP_WAIT(n)  asm volatile("cp.async.wait_group %0;" :: "n"(n) : "memory")

static __device__ __forceinline__ uint32_t lds32(uint32_t addr) {
    uint32_t v;
    asm volatile("ld.shared.b32 %0, [%1];" : "=r"(v) : "r"(addr));
    return v;
}
static __device__ __forceinline__ void mma_bf16(float* c, const uint32_t* a,
                                                const uint32_t* b) {
    asm volatile(
        "mma.sync.aligned.m16n8k16.row.col.f32.bf16.bf16.f32 "
        "{%0,%1,%2,%3}, {%4,%5,%6,%7}, {%8,%9}, {%0,%1,%2,%3};"
        : "+f"(c[0]), "+f"(c[1]), "+f"(c[2]), "+f"(c[3])
        : "r"(a[0]), "r"(a[1]), "r"(a[2]), "r"(a[3]), "r"(b[0]), "r"(b[1]));
}
// conflict-free 16B-unit swizzle within a 64B row
static __device__ __forceinline__ int swz(int row, int u) {
    return (u ^ row ^ (row >> 2)) & 3;
}

// ============================================================================
// Prep: split fp32 -> bf16 hi + bf16 lo  (a = hi + lo + O(2^-18 a))
// ============================================================================
__global__ void split_emb_kernel(const float* __restrict__ src) {
    int i = blockIdx.x * blockDim.x + threadIdx.x;
    if (i >= 4096 * 256 / 4) return;
    float4 v = ((const float4*)src)[i];
    float f[4] = {v.x, v.y, v.z, v.w};
    __nv_bfloat16 h[4], l[4];
#pragma unroll
    for (int j = 0; j < 4; j++) {
        h[j] = __float2bfloat16(f[j]);
        l[j] = __float2bfloat16(f[j] - __bfloat162float(h[j]));
    }
    ((__nv_bfloat162*)g_emb_hi)[2 * i + 0] = __nv_bfloat162(h[0], h[1]);
    ((__nv_bfloat162*)g_emb_hi)[2 * i + 1] = __nv_bfloat162(h[2], h[3]);
    ((__nv_bfloat162*)g_emb_lo)[2 * i + 0] = __nv_bfloat162(l[0], l[1]);
    ((__nv_bfloat162*)g_emb_lo)[2 * i + 1] = __nv_bfloat162(l[2], l[3]);
}
__global__ void split_q_kernel(const float* __restrict__ src) {
    int i = blockIdx.x * blockDim.x + threadIdx.x;
    if (i >= 65536 * 256 / 4) return;
    float4 v = ((const float4*)src)[i];
    float f[4] = {v.x, v.y, v.z, v.w};
    __nv_bfloat16 h[4], l[4];
#pragma unroll
    for (int j = 0; j < 4; j++) {
        h[j] = __float2bfloat16(f[j]);
        l[j] = __float2bfloat16(f[j] - __bfloat162float(h[j]));
    }
    ((__nv_bfloat162*)g_q_hi)[2 * i + 0] = __nv_bfloat162(h[0], h[1]);
    ((__nv_bfloat162*)g_q_hi)[2 * i + 1] = __nv_bfloat162(h[2], h[3]);
    ((__nv_bfloat162*)g_q_lo)[2 * i + 0] = __nv_bfloat162(l[0], l[1]);
    ((__nv_bfloat162*)g_q_lo)[2 * i + 1] = __nv_bfloat162(l[2], l[3]);
}

// ============================================================================
// Stage 1: sim = emb @ queue^T via mma.sync bf16 (3-term split), fused argmax.
// Grid (32, NSPLIT), 256 threads = 8 warps (2m x 4n), warp tile 64x32.
// K' = 768 streamed in 24 chunks of 32, cp.async double buffer.
// ============================================================================
__global__ __launch_bounds__(256)
void nn_argmax_mma_kernel()
{
    __shared__ __align__(16) char sAbuf[2][8192];   // 128 rows x 64B (BK=32 bf16)
    __shared__ __align__(16) char sBbuf[2][8192];
    __shared__ float rv[128][4];
    __shared__ int   ri[128][4];

    const uint32_t sA = smem_to_u32(sAbuf);
    const uint32_t sB = smem_to_u32(sBbuf);

    const int tid  = threadIdx.x;
    const int wid  = tid >> 5;
    const int lane = tid & 31;
    const int qrow = lane >> 2;
    const int qcol = lane & 3;
    const int wm   = (wid >> 2) * 64;     // warp m offset (0 or 64)
    const int wn   = (wid & 3) * 32;      // warp n offset
    const int m0   = blockIdx.x * 128;
    const int by   = blockIdx.y;

    // running argmax: slot (i, rh) -> row = wm + i*16 + rh*8 + qrow
    float best[8];
    int   bidx[8];
#pragma unroll
    for (int s = 0; s < 8; s++) { best[s] = -INFINITY; bidx[s] = 0x7fffffff; }

    // per-thread load coords (2 x 16B units for A and B each per chunk)
    const int lrow0 = (tid * 2) >> 2;        // unit u = tid*2 + v
    // chunk source tables resolved in the loop

    for (int c = by; c < NTILES; c += NSPLIT) {
        const int n0 = c * 128;

        float acc[4][4][4];
#pragma unroll
        for (int i = 0; i < 4; i++)
#pragma unroll
            for (int j = 0; j < 4; j++)
#pragma unroll
                for (int k = 0; k < 4; k++) acc[i][j][k] = 0.f;

        // ---- issue chunk 0 ----
        {
            const int t = 0;
            const __nv_bfloat16* asrc = g_emb_hi;
            const __nv_bfloat16* bsrc = g_q_hi;
            const int k0 = 0;
#pragma unroll
            for (int v = 0; v < 2; v++) {
                const int u = tid * 2 + v;
                const int row = u >> 2, un = u & 3;
                cp16(sA + row * 64 + (swz(row, un) << 4),
                     asrc + (((size_t)(m0 + row)) << 8) + k0 + un * 8);
                cp16(sB + row * 64 + (swz(row, un) << 4),
                     bsrc + (((size_t)(n0 + row)) << 8) + k0 + un * 8);
            }
            CP_COMMIT();
            (void)t;
        }

#pragma unroll 1
        for (int t = 0; t < NCHUNK; t++) {
            if (t + 1 < NCHUNK) {
                const int tn = t + 1;
                const __nv_bfloat16* asrc = (tn < 16) ? g_emb_hi : g_emb_lo;
                const __nv_bfloat16* bsrc = (tn >= 8 && tn < 16) ? g_q_lo : g_q_hi;
                const int k0 = (tn & 7) * 32;
                const uint32_t bo = (uint32_t)((tn & 1) * 8192);
#pragma unroll
                for (int v = 0; v < 2; v++) {
                    const int u = tid * 2 + v;
                    const int row = u >> 2, un = u & 3;
                    cp16(sA + bo + row * 64 + (swz(row, un) << 4),
                         asrc + (((size_t)(m0 + row)) << 8) + k0 + un * 8);
                    cp16(sB + bo + row * 64 + (swz(row, un) << 4),
                         bsrc + (((size_t)(n0 + row)) << 8) + k0 + un * 8);
                }
                CP_COMMIT();
                CP_WAIT(1);
            } else {
                CP_WAIT(0);
            }
            __syncthreads();

            const uint32_t sAb = sA + (uint32_t)((t & 1) * 8192);
            const uint32_t sBb = sB + (uint32_t)((t & 1) * 8192);

#pragma unroll
            for (int s = 0; s < 2; s++) {
                const int u0 = 2 * s, u1 = 2 * s + 1;
                uint32_t bf[4][2];
#pragma unroll
                for (int j = 0; j < 4; j++) {
                    const int n = wn + j * 8 + qrow;
                    bf[j][0] = lds32(sBb + n * 64 + (swz(n, u0) << 4) + qcol * 4);
                    bf[j][1] = lds32(sBb + n * 64 + (swz(n, u1) << 4) + qcol * 4);
                }
#pragma unroll
                for (int i = 0; i < 4; i++) {
                    const int r0 = wm + i * 16 + qrow;
                    const int r1 = r0 + 8;
                    uint32_t af[4];
                    af[0] = lds32(sAb + r0 * 64 + (swz(r0, u0) << 4) + qcol * 4);
                    af[1] = lds32(sAb + r1 * 64 + (swz(r1, u0) << 4) + qcol * 4);
                    af[2] = lds32(sAb + r0 * 64 + (swz(r0, u1) << 4) + qcol * 4);
                    af[3] = lds32(sAb + r1 * 64 + (swz(r1, u1) << 4) + qcol * 4);
#pragma unroll
                    for (int j = 0; j < 4; j++)
                        mma_bf16(acc[i][j], af, bf[j]);
                }
            }
            __syncthreads();
        }

        // ---- fused running argmax (cols ascend within slot => strict > = first) ----
#pragma unroll
        for (int i = 0; i < 4; i++) {
#pragma unroll
            for (int rh = 0; rh < 2; rh++) {
                const int slot = i * 2 + rh;
                float bv = best[slot]; int bi = bidx[slot];
#pragma unroll
                for (int j = 0; j < 4; j++) {
#pragma unroll
                    for (int kb = 0; kb < 2; kb++) {
                        const float v = acc[i][j][rh * 2 + kb];
                        const int col = n0 + wn + j * 8 + qcol * 2 + kb;
                        if (v > bv) { bv = v; bi = col; }
                    }
                }
                best[slot] = bv; bidx[slot] = bi;
            }
        }
    }

    // ---- reduce across qcol lanes (same rows), then across n-warps ----
#pragma unroll
    for (int s = 0; s < 8; s++) {
        float v = best[s]; int id = bidx[s];
#pragma unroll
        for (int o = 1; o <= 2; o <<= 1) {
            float ov = __shfl_xor_sync(0xffffffffu, v, o);
            int   oi = __shfl_xor_sync(0xffffffffu, id, o);
            if (ov > v || (ov == v && oi < id)) { v = ov; id = oi; }
        }
        if (qcol == 0) {
            const int row = wm + (s >> 1) * 16 + (s & 1) * 8 + qrow;
            rv[row][wid & 3] = v;
            ri[row][wid & 3] = id;
        }
    }
    __syncthreads();
    if (tid < 128) {
        float bv = -INFINITY; int bi = 0x7fffffff;
#pragma unroll
        for (int w = 0; w < 4; w++) {
            const float v = rv[tid][w]; const int id = ri[tid][w];
            if (v > bv || (v == bv && id < bi)) { bv = v; bi = id; }
        }
        g_pmax[(size_t)(m0 + tid) * NSPLIT + by] = bv;
        g_pidx[(size_t)(m0 + tid) * NSPLIT + by] = bi;
    }
    (void)lrow0;
}

// Merge NSPLIT partials (idx tie-break => first occurrence, matches jnp.argmax)
__global__ void merge_argmax_kernel(int B)
{
    int i = blockIdx.x * blockDim.x + threadIdx.x;
    if (i >= B) return;
    float bv = -INFINITY; int bi = 0x7fffffff;
#pragma unroll
    for (int s = 0; s < NSPLIT; s++) {
        float v = g_pmax[(size_t)i * NSPLIT + s];
        int  id = g_pidx[(size_t)i * NSPLIT + s];
        if (v > bv || (v == bv && id < bi)) { bv = v; bi = id; }
    }
    g_nn[i] = bi;
}

// ============================================================================
// Stage 2a: logits[s][i][j] = 10 * dot(queue[nn[s*half+i]], preds[(1-s)*half+j])
// ============================================================================
__global__ __launch_bounds__(256)
void logits_kernel(const float* __restrict__ queue, const float* __restrict__ preds,
                   int half)
{
    __shared__ int   idx_s[BM2];
    __shared__ float As[BK2][BM2 + 4];
    __shared__ float Bs[BK2][BN2 + 4];

    const int tid = threadIdx.x;
    const int tx = tid & 15;
    const int ty = tid >> 4;
    const int s  = blockIdx.z;
    const int m0 = blockIdx.x * BM2;
    const int n0 = blockIdx.y * BN2;

    if (tid < BM2) idx_s[tid] = g_nn[s * half + m0 + tid];
    __syncthreads();

    const float* pb = preds + (size_t)(1 - s) * half * D;
    const int lm  = tid >> 2;
    const int lk4 = (tid & 3) * 4;

    float acc[4][4] = {};

    for (int k0 = 0; k0 < D; k0 += BK2) {
        float4 av = *(const float4*)&queue[(size_t)idx_s[lm] * D + k0 + lk4];
        float4 bv = *(const float4*)&pb[(size_t)(n0 + lm) * D + k0 + lk4];
        __syncthreads();
        As[lk4 + 0][lm] = av.x; As[lk4 + 1][lm] = av.y;
        As[lk4 + 2][lm] = av.z; As[lk4 + 3][lm] = av.w;
        Bs[lk4 + 0][lm] = bv.x; Bs[lk4 + 1][lm] = bv.y;
        Bs[lk4 + 2][lm] = bv.z; Bs[lk4 + 3][lm] = bv.w;
        __syncthreads();
#pragma unroll
        for (int k = 0; k < BK2; k++) {
            float4 a = *(const float4*)&As[k][ty * 4];
            float4 b = *(const float4*)&Bs[k][tx * 4];
            float am[4] = {a.x, a.y, a.z, a.w};
            float bn[4] = {b.x, b.y, b.z, b.w};
#pragma unroll
            for (int i = 0; i < 4; i++)
#pragma unroll
                for (int j = 0; j < 4; j++)
                    acc[i][j] += am[i] * bn[j];
        }
    }

#pragma unroll
    for (int i = 0; i < 4; i++) {
        const int row = s * half + m0 + ty * 4 + i;
        float4 o = make_float4(acc[i][0] * 10.f, acc[i][1] * 10.f,
                               acc[i][2] * 10.f, acc[i][3] * 10.f);
        *(float4*)&g_logits[(size_t)row * half + n0 + tx * 4] = o;
    }
}

// ============================================================================
// Stage 2b: per-row logsumexp(row) - row[diag]
// ============================================================================
__global__ __launch_bounds__(256)
void ce_row_kernel(int half)
{
    __shared__ float red[8];
    const int row = blockIdx.x;
    const int tid = threadIdx.x;
    const float* L = g_logits + (size_t)row * half;

    float m = -INFINITY;
    for (int j = tid; j < half; j += 256) m = fmaxf(m, L[j]);
#pragma unroll
    for (int o = 16; o; o >>= 1) m = fmaxf(m, __shfl_xor_sync(0xffffffffu, m, o));
    if ((tid & 31) == 0) red[tid >> 5] = m;
    __syncthreads();
    if (tid == 0) {
        float tt = red[0];
#pragma unroll
        for (int w = 1; w < 8; w++) tt = fmaxf(tt, red[w]);
        red[0] = tt;
    }
    __syncthreads();
    const float bm = red[0];
    __syncthreads();

    float sum = 0.f;
    for (int j = tid; j < half; j += 256) sum += expf(L[j] - bm);
#pragma unroll
    for (int o = 16; o; o >>= 1) sum += __shfl_xor_sync(0xffffffffu, sum, o);
    if ((tid & 31) == 0) red[tid >> 5] = sum;
    __syncthreads();
    if (tid == 0) {
        float tt = 0.f;
#pragma unroll
        for (int w = 0; w < 8; w++) tt += red[w];
        int diag = row % half;
        g_rowterm[row] = logf(tt) + bm - L[diag];
    }
}

__global__ __launch_bounds__(256)
void final_kernel(float* __restrict__ out, int total)
{
    __shared__ float red[8];
    const int tid = threadIdx.x;
    float s = 0.f;
    for (int i = tid; i < total; i += 256) s += g_rowterm[i];
#pragma unroll
    for (int o = 16; o; o >>= 1) s += __shfl_xor_sync(0xffffffffu, s, o);
    if ((tid & 31) == 0) red[tid >> 5] = s;
    __syncthreads();
    if (tid == 0) {
        float tt = 0.f;
#pragma unroll
        for (int w = 0; w < 8; w++) tt += red[w];
        out[0] = tt / (float)total;
    }
}

// ============================================================================
extern "C" void kernel_launch(void* const* d_in, const int* in_sizes, int n_in,
                              void* d_out, int out_size)
{
    const float* emb   = (const float*)d_in[0];   // [4096, 256]
    const float* preds = (const float*)d_in[1];   // [4096, 256]
    const float* queue = (const float*)d_in[2];   // [65536, 256]

    const int B = in_sizes[0] / D;     // 4096
    const int half = B / 2;            // 2048

    split_emb_kernel<<<(4096 * 256 / 4 + 255) / 256, 256>>>(emb);
    split_q_kernel<<<(65536 * 256 / 4 + 255) / 256, 256>>>(queue);
    nn_argmax_mma_kernel<<<dim3(B / 128, NSPLIT), 256>>>();
    merge_argmax_kernel<<<(B + 255) / 256, 256>>>(B);
    logits_kernel<<<dim3(half / BM2, half / BN2, 2), 256>>>(queue, preds, half);
    ce_row_kernel<<<2 * half, 256>>>(half);
    final_kernel<<<1, 256>>>((float*)d_out, 2 * half);
}

// round 7
// speedup vs baseline: 3.0317x; 2.4707x over previous
#include <cuda_runtime.h>
#include <cuda_bf16.h>
#include <math.h>
#include <cstdint>

// ---------------- problem constants ----------------
#define D        256
#define NSPLIT   9
#define NTILES   512          // Q / 128
#define BM2      64
#define BN2      64
#define BK2      16

// ---------------- static device scratch ----------------
__device__ __align__(16) __nv_bfloat16 g_emb_hi[4096 * 256];
__device__ __align__(16) __nv_bfloat16 g_q_hi[65536 * 256];
__device__ float g_tmax[(size_t)4096 * NTILES];     // 8 MB: per-row per-tile hi-max
__device__ int   g_nn[4096];
__device__ float g_logits[2u * 2048u * 2048u];
__device__ float g_rowterm[4096];

// ---------------- PTX helpers (plain sm_103-safe: sm_80+ features only) ----
static __device__ __forceinline__ uint32_t smem_to_u32(const void* p) {
    uint32_t a;
    asm("{ .reg .u64 t; cvta.to.shared.u64 t, %1; cvt.u32.u64 %0, t; }"
        : "=r"(a) : "l"(p));
    return a;
}
static __device__ __forceinline__ void cp16(uint32_t dst, const void* src) {
    asm volatile("cp.async.cg.shared.global [%0], [%1], 16;"
                 :: "r"(dst), "l"(src) : "memory");
}
#define CP_COMMIT() asm volatile("cp.async.commit_group;" ::: "memory")
#define CP_WAIT(n)  asm volatile("cp.async.wait_group %0;" :: "n"(n) : "memory")

static __device__ __forceinline__ uint32_t lds32(uint32_t addr) {
    uint32_t v;
    asm volatile("ld.shared.b32 %0, [%1];" : "=r"(v) : "r"(addr));
    return v;
}
static __device__ __forceinline__ void mma_bf16(float* c, const uint32_t* a,
                                                const uint32_t* b) {
    asm volatile(
        "mma.sync.aligned.m16n8k16.row.col.f32.bf16.bf16.f32 "
        "{%0,%1,%2,%3}, {%4,%5,%6,%7}, {%8,%9}, {%0,%1,%2,%3};"
        : "+f"(c[0]), "+f"(c[1]), "+f"(c[2]), "+f"(c[3])
        : "r"(a[0]), "r"(a[1]), "r"(a[2]), "r"(a[3]), "r"(b[0]), "r"(b[1]));
}
// conflict-free 16B-unit swizzle within a 64B row (verified in R5)
static __device__ __forceinline__ int swz(int row, int u) {
    return (u ^ row ^ (row >> 2)) & 3;
}

// ============================================================================
// Prep: fp32 -> bf16 (hi part only needed now)
// ============================================================================
__global__ void split_emb_kernel(const float* __restrict__ src) {
    int i = blockIdx.x * blockDim.x + threadIdx.x;
    if (i >= 4096 * 256 / 4) return;
    float4 v = ((const float4*)src)[i];
    ((__nv_bfloat162*)g_emb_hi)[2 * i + 0] =
        __nv_bfloat162(__float2bfloat16(v.x), __float2bfloat16(v.y));
    ((__nv_bfloat162*)g_emb_hi)[2 * i + 1] =
        __nv_bfloat162(__float2bfloat16(v.z), __float2bfloat16(v.w));
}
__global__ void split_q_kernel(const float* __restrict__ src) {
    int i = blockIdx.x * blockDim.x + threadIdx.x;
    if (i >= 65536 * 256 / 4) return;
    float4 v = ((const float4*)src)[i];
    ((__nv_bfloat162*)g_q_hi)[2 * i + 0] =
        __nv_bfloat162(__float2bfloat16(v.x), __float2bfloat16(v.y));
    ((__nv_bfloat162*)g_q_hi)[2 * i + 1] =
        __nv_bfloat162(__float2bfloat16(v.z), __float2bfloat16(v.w));
}

// ============================================================================
// Pass 1: hi-only sim tile-max. Grid (32, NSPLIT), 256 thr = 8 warps (2m x 4n).
// A tile (128x256 bf16, 64KB) resident in smem; B streamed via 3-stage ring.
// Writes g_tmax[row][tile] = max over the 128 cols of that tile.
// ============================================================================
// dynamic smem layout: A[8][128][64B] = 65536, Bring[3][8192] = 24576, rv 2048
#define SM_A     0
#define SM_B     65536
#define SM_RV    (65536 + 3 * 8192)
#define SM_TOT   (SM_RV + 128 * 4 * 4)

__global__ __launch_bounds__(256)
void pass1_mma_kernel()
{
    extern __shared__ __align__(16) char smem[];
    const uint32_t sA = smem_to_u32(smem) + SM_A;
    const uint32_t sB = smem_to_u32(smem) + SM_B;
    float (*rv)[4] = (float (*)[4])(smem + SM_RV);

    const int tid  = threadIdx.x;
    const int wid  = tid >> 5;
    const int lane = tid & 31;
    const int qrow = lane >> 2;
    const int qcol = lane & 3;
    const int wm   = (wid >> 2) * 64;
    const int wn   = (wid & 3) * 32;
    const int m0   = blockIdx.x * 128;
    const int by   = blockIdx.y;

    const int T = (NTILES - by + NSPLIT - 1) / NSPLIT;   // tiles for this CTA
    const int G = T * 8;                                  // k32-chunks total

    // ---- load resident A tile: 8 chunks x 512 units of 16B ----
#pragma unroll
    for (int i = 0; i < 16; i++) {
        const int w = i * 256 + tid;
        const int kc = w >> 9, wu = w & 511;
        const int row = wu >> 2, un = wu & 3;
        cp16(sA + kc * 8192 + row * 64 + (swz(row, un) << 4),
             g_emb_hi + (((size_t)(m0 + row)) << 8) + kc * 32 + un * 8);
    }
    CP_COMMIT();

    // ---- prime B chunks 0,1 ----
#pragma unroll
    for (int g0 = 0; g0 < 2; g0++) {
        const int t = g0 >> 3, kc = g0 & 7;
        const int n0 = (by + t * NSPLIT) * 128;
#pragma unroll
        for (int v = 0; v < 2; v++) {
            const int u = tid * 2 + v;
            const int row = u >> 2, un = u & 3;
            cp16(sB + (g0 % 3) * 8192 + row * 64 + (swz(row, un) << 4),
                 g_q_hi + (((size_t)(n0 + row)) << 8) + kc * 32 + un * 8);
        }
        CP_COMMIT();
    }

    float acc[4][4][4];
#pragma unroll
    for (int i = 0; i < 4; i++)
#pragma unroll
        for (int j = 0; j < 4; j++)
#pragma unroll
            for (int k = 0; k < 4; k++) acc[i][j][k] = 0.f;

#pragma unroll 1
    for (int g = 0; g < G; g++) {
        __syncthreads();             // closes compute(g-1): safe to refill its buf
        if (g + 2 < G) {
            const int gn = g + 2;
            const int t = gn >> 3, kc = gn & 7;
            const int n0 = (by + t * NSPLIT) * 128;
#pragma unroll
            for (int v = 0; v < 2; v++) {
                const int u = tid * 2 + v;
                const int row = u >> 2, un = u & 3;
                cp16(sB + (gn % 3) * 8192 + row * 64 + (swz(row, un) << 4),
                     g_q_hi + (((size_t)(n0 + row)) << 8) + kc * 32 + un * 8);
            }
            CP_COMMIT();
            CP_WAIT(2);
        } else if (g + 2 == G) {
            CP_WAIT(1);
        } else {
            CP_WAIT(0);
        }
        __syncthreads();             // chunk g data visible to all

        const int kc = g & 7;
        const uint32_t sAb = sA + (uint32_t)(kc * 8192);
        const uint32_t sBb = sB + (uint32_t)((g % 3) * 8192);

#pragma unroll
        for (int s = 0; s < 2; s++) {
            const int u0 = 2 * s, u1 = 2 * s + 1;
            uint32_t bf[4][2];
#pragma unroll
            for (int j = 0; j < 4; j++) {
                const int n = wn + j * 8 + qrow;
                bf[j][0] = lds32(sBb + n * 64 + (swz(n, u0) << 4) + qcol * 4);
                bf[j][1] = lds32(sBb + n * 64 + (swz(n, u1) << 4) + qcol * 4);
            }
#pragma unroll
            for (int i = 0; i < 4; i++) {
                const int r0 = wm + i * 16 + qrow;
                const int r1 = r0 + 8;
                uint32_t af[4];
                af[0] = lds32(sAb + r0 * 64 + (swz(r0, u0) << 4) + qcol * 4);
                af[1] = lds32(sAb + r1 * 64 + (swz(r1, u0) << 4) + qcol * 4);
                af[2] = lds32(sAb + r0 * 64 + (swz(r0, u1) << 4) + qcol * 4);
                af[3] = lds32(sAb + r1 * 64 + (swz(r1, u1) << 4) + qcol * 4);
#pragma unroll
                for (int j = 0; j < 4; j++)
                    mma_bf16(acc[i][j], af, bf[j]);
            }
        }

        if (kc == 7) {
            // ---- tile epilogue: per-row max -> g_tmax ----
            const int tile_c = by + (g >> 3) * NSPLIT;
#pragma unroll
            for (int i = 0; i < 4; i++) {
#pragma unroll
                for (int rh = 0; rh < 2; rh++) {
                    float bv = -INFINITY;
#pragma unroll
                    for (int j = 0; j < 4; j++) {
                        bv = fmaxf(bv, acc[i][j][rh * 2 + 0]);
                        bv = fmaxf(bv, acc[i][j][rh * 2 + 1]);
                    }
                    bv = fmaxf(bv, __shfl_xor_sync(0xffffffffu, bv, 1));
                    bv = fmaxf(bv, __shfl_xor_sync(0xffffffffu, bv, 2));
                    if (qcol == 0)
                        rv[wm + i * 16 + rh * 8 + qrow][wid & 3] = bv;
                }
            }
            __syncthreads();
            if (tid < 128) {
                float bv = fmaxf(fmaxf(rv[tid][0], rv[tid][1]),
                                 fmaxf(rv[tid][2], rv[tid][3]));
                g_tmax[(size_t)(m0 + tid) * NTILES + tile_c] = bv;
            }
#pragma unroll
            for (int i = 0; i < 4; i++)
#pragma unroll
                for (int j = 0; j < 4; j++)
#pragma unroll
                    for (int k = 0; k < 4; k++) acc[i][j][k] = 0.f;
        }
    }
}

// ============================================================================
// Pass 2: per row — margin from ||a||, pick candidate tiles, exact fp32
// argmax over their columns (index tie-break -> first occurrence).
// ============================================================================
__global__ __launch_bounds__(256)
void argmax_exact_kernel(const float* __restrict__ emb,
                         const float* __restrict__ queue)
{
    __shared__ float arow[256];
    __shared__ float tmax_s[NTILES];
    __shared__ float red[8];
    __shared__ int   redi[8];

    const int r   = blockIdx.x;
    const int tid = threadIdx.x;

    arow[tid] = emb[(size_t)r * 256 + tid];
    tmax_s[tid]       = g_tmax[(size_t)r * NTILES + tid];
    tmax_s[tid + 256] = g_tmax[(size_t)r * NTILES + tid + 256];
    __syncthreads();

    // ||a||^2 and global hi-max
    float p = arow[tid] * arow[tid];
    float m = fmaxf(tmax_s[tid], tmax_s[tid + 256]);
#pragma unroll
    for (int o = 16; o; o >>= 1) {
        p += __shfl_xor_sync(0xffffffffu, p, o);
        m = fmaxf(m, __shfl_xor_sync(0xffffffffu, m, o));
    }
    if ((tid & 31) == 0) { red[tid >> 5] = p; }
    __syncthreads();
    if (tid == 0) {
        float s = 0.f;
#pragma unroll
        for (int w = 0; w < 8; w++) s += red[w];
        red[0] = s;
    }
    __syncthreads();
    const float norm = sqrtf(red[0]);
    __syncthreads();
    if ((tid & 31) == 0) red[tid >> 5] = m;
    __syncthreads();
    if (tid == 0) {
        float mm = red[0];
#pragma unroll
        for (int w = 1; w < 8; w++) mm = fmaxf(mm, red[w]);
        red[0] = mm;
    }
    __syncthreads();
    const float M = red[0];
    // |sim - sim_hi| <= 2^-8 * ||a||; threshold = M - 2*margin (5% slack)
    const float thr = M - norm * (2.1f / 128.0f);
    __syncthreads();

    float best_v = -INFINITY;
    int   best_i = 0x7fffffff;

    for (int t = 0; t < NTILES; t++) {
        if (tmax_s[t] < thr) continue;
        if (tid < 128) {
            const int col = t * 128 + tid;
            const float4* qr = (const float4*)(queue + (size_t)col * 256);
            float s = 0.f;
#pragma unroll 8
            for (int k = 0; k < 64; k++) {
                const float4 q4 = qr[k];
                s = fmaf(arow[4 * k + 0], q4.x, s);
                s = fmaf(arow[4 * k + 1], q4.y, s);
                s = fmaf(arow[4 * k + 2], q4.z, s);
                s = fmaf(arow[4 * k + 3], q4.w, s);
            }
            if (s > best_v || (s == best_v && col < best_i)) {
                best_v = s; best_i = col;
            }
        }
    }

    // reduce (value, min index on ties) across threads
#pragma unroll
    for (int o = 16; o; o >>= 1) {
        const float ov = __shfl_xor_sync(0xffffffffu, best_v, o);
        const int   oi = __shfl_xor_sync(0xffffffffu, best_i, o);
        if (ov > best_v || (ov == best_v && oi < best_i)) {
            best_v = ov; best_i = oi;
        }
    }
    if ((tid & 31) == 0) { red[tid >> 5] = best_v; redi[tid >> 5] = best_i; }
    __syncthreads();
    if (tid == 0) {
        float bv = red[0]; int bi = redi[0];
#pragma unroll
        for (int w = 1; w < 8; w++) {
            if (red[w] > bv || (red[w] == bv && redi[w] < bi)) {
                bv = red[w]; bi = redi[w];
            }
        }
        g_nn[r] = bi;
    }
}

// ============================================================================
// Stage 2a: logits[s][i][j] = 10 * dot(queue[nn[s*half+i]], preds[(1-s)*half+j])
// ============================================================================
__global__ __launch_bounds__(256)
void logits_kernel(const float* __restrict__ queue, const float* __restrict__ preds,
                   int half)
{
    __shared__ int   idx_s[BM2];
    __shared__ float As[BK2][BM2 + 4];
    __shared__ float Bs[BK2][BN2 + 4];

    const int tid = threadIdx.x;
    const int tx = tid & 15;
    const int ty = tid >> 4;
    const int s  = blockIdx.z;
    const int m0 = blockIdx.x * BM2;
    const int n0 = blockIdx.y * BN2;

    if (tid < BM2) idx_s[tid] = g_nn[s * half + m0 + tid];
    __syncthreads();

    const float* pb = preds + (size_t)(1 - s) * half * D;
    const int lm  = tid >> 2;
    const int lk4 = (tid & 3) * 4;

    float acc[4][4] = {};

    for (int k0 = 0; k0 < D; k0 += BK2) {
        float4 av = *(const float4*)&queue[(size_t)idx_s[lm] * D + k0 + lk4];
        float4 bv = *(const float4*)&pb[(size_t)(n0 + lm) * D + k0 + lk4];
        __syncthreads();
        As[lk4 + 0][lm] = av.x; As[lk4 + 1][lm] = av.y;
        As[lk4 + 2][lm] = av.z; As[lk4 + 3][lm] = av.w;
        Bs[lk4 + 0][lm] = bv.x; Bs[lk4 + 1][lm] = bv.y;
        Bs[lk4 + 2][lm] = bv.z; Bs[lk4 + 3][lm] = bv.w;
        __syncthreads();
#pragma unroll
        for (int k = 0; k < BK2; k++) {
            float4 a = *(const float4*)&As[k][ty * 4];
            float4 b = *(const float4*)&Bs[k][tx * 4];
            float am[4] = {a.x, a.y, a.z, a.w};
            float bn[4] = {b.x, b.y, b.z, b.w};
#pragma unroll
            for (int i = 0; i < 4; i++)
#pragma unroll
                for (int j = 0; j < 4; j++)
                    acc[i][j] += am[i] * bn[j];
        }
    }

#pragma unroll
    for (int i = 0; i < 4; i++) {
        const int row = s * half + m0 + ty * 4 + i;
        float4 o = make_float4(acc[i][0] * 10.f, acc[i][1] * 10.f,
                               acc[i][2] * 10.f, acc[i][3] * 10.f);
        *(float4*)&g_logits[(size_t)row * half + n0 + tx * 4] = o;
    }
}

// ============================================================================
// Stage 2b: per-row logsumexp(row) - row[diag]
// ============================================================================
__global__ __launch_bounds__(256)
void ce_row_kernel(int half)
{
    __shared__ float red[8];
    const int row = blockIdx.x;
    const int tid = threadIdx.x;
    const float* L = g_logits + (size_t)row * half;

    float m = -INFINITY;
    for (int j = tid; j < half; j += 256) m = fmaxf(m, L[j]);
#pragma unroll
    for (int o = 16; o; o >>= 1) m = fmaxf(m, __shfl_xor_sync(0xffffffffu, m, o));
    if ((tid & 31) == 0) red[tid >> 5] = m;
    __syncthreads();
    if (tid == 0) {
        float tt = red[0];
#pragma unroll
        for (int w = 1; w < 8; w++) tt = fmaxf(tt, red[w]);
        red[0] = tt;
    }
    __syncthreads();
    const float bm = red[0];
    __syncthreads();

    float sum = 0.f;
    for (int j = tid; j < half; j += 256) sum += expf(L[j] - bm);
#pragma unroll
    for (int o = 16; o; o >>= 1) sum += __shfl_xor_sync(0xffffffffu, sum, o);
    if ((tid & 31) == 0) red[tid >> 5] = sum;
    __syncthreads();
    if (tid == 0) {
        float tt = 0.f;
#pragma unroll
        for (int w = 0; w < 8; w++) tt += red[w];
        int diag = row % half;
        g_rowterm[row] = logf(tt) + bm - L[diag];
    }
}

__global__ __launch_bounds__(256)
void final_kernel(float* __restrict__ out, int total)
{
    __shared__ float red[8];
    const int tid = threadIdx.x;
    float s = 0.f;
    for (int i = tid; i < total; i += 256) s += g_rowterm[i];
#pragma unroll
    for (int o = 16; o; o >>= 1) s += __shfl_xor_sync(0xffffffffu, s, o);
    if ((tid & 31) == 0) red[tid >> 5] = s;
    __syncthreads();
    if (tid == 0) {
        float tt = 0.f;
#pragma unroll
        for (int w = 0; w < 8; w++) tt += red[w];
        out[0] = tt / (float)total;
    }
}

// ============================================================================
extern "C" void kernel_launch(void* const* d_in, const int* in_sizes, int n_in,
                              void* d_out, int out_size)
{
    const float* emb   = (const float*)d_in[0];   // [4096, 256]
    const float* preds = (const float*)d_in[1];   // [4096, 256]
    const float* queue = (const float*)d_in[2];   // [65536, 256]

    const int B = in_sizes[0] / D;     // 4096
    const int half = B / 2;            // 2048

    cudaFuncSetAttribute(pass1_mma_kernel,
                         cudaFuncAttributeMaxDynamicSharedMemorySize, SM_TOT);

    split_emb_kernel<<<(4096 * 256 / 4 + 255) / 256, 256>>>(emb);
    split_q_kernel<<<(65536 * 256 / 4 + 255) / 256, 256>>>(queue);
    pass1_mma_kernel<<<dim3(B / 128, NSPLIT), 256, SM_TOT>>>();
    argmax_exact_kernel<<<B, 256>>>(emb, queue);
    logits_kernel<<<dim3(half / BM2, half / BN2, 2), 256>>>(queue, preds, half);
    ce_row_kernel<<<2 * half, 256>>>(half);
    final_kernel<<<1, 256>>>((float*)d_out, 2 * half);
}

// round 8
// speedup vs baseline: 5.1191x; 1.6885x over previous
#include <cuda_runtime.h>
#include <cuda_bf16.h>
#include <math.h>
#include <cstdint>

// ---------------- problem constants ----------------
#define D        256
#define NSPLIT   9
#define NTILES   512          // Q / 128
#define BM2      64
#define BN2      64
#define BK2      16
#define WL_CAP   (4096 * 512)

// ---------------- static device scratch ----------------
__device__ __align__(16) __nv_bfloat16 g_emb_hi[4096 * 256];
__device__ __align__(16) __nv_bfloat16 g_q_hi[65536 * 256];
__device__ float g_tmax[(size_t)4096 * NTILES];     // 8 MB per-row per-tile hi-max
__device__ int   g_nn[4096];
__device__ float g_logits[2u * 2048u * 2048u];
__device__ float g_rowterm[4096];
__device__ unsigned long long g_best[4096];
__device__ uint32_t g_wl[WL_CAP];                   // (row<<9)|tile
__device__ int g_cnt;

// ---------------- PTX helpers (plain sm_103-safe: sm_80+ features only) ----
static __device__ __forceinline__ uint32_t smem_to_u32(const void* p) {
    uint32_t a;
    asm("{ .reg .u64 t; cvta.to.shared.u64 t, %1; cvt.u32.u64 %0, t; }"
        : "=r"(a) : "l"(p));
    return a;
}
static __device__ __forceinline__ void cp16(uint32_t dst, const void* src) {
    asm volatile("cp.async.cg.shared.global [%0], [%1], 16;"
                 :: "r"(dst), "l"(src) : "memory");
}
#define CP_COMMIT() asm volatile("cp.async.commit_group;" ::: "memory")
#define CP_WAIT(n)  asm volatile("cp.async.wait_group %0;" :: "n"(n) : "memory")

static __device__ __forceinline__ uint32_t lds32(uint32_t addr) {
    uint32_t v;
    asm volatile("ld.shared.b32 %0, [%1];" : "=r"(v) : "r"(addr));
    return v;
}
static __device__ __forceinline__ void mma_bf16(float* c, const uint32_t* a,
                                                const uint32_t* b) {
    asm volatile(
        "mma.sync.aligned.m16n8k16.row.col.f32.bf16.bf16.f32 "
        "{%0,%1,%2,%3}, {%4,%5,%6,%7}, {%8,%9}, {%0,%1,%2,%3};"
        : "+f"(c[0]), "+f"(c[1]), "+f"(c[2]), "+f"(c[3])
        : "r"(a[0]), "r"(a[1]), "r"(a[2]), "r"(a[3]), "r"(b[0]), "r"(b[1]));
}
// conflict-free 16B-unit swizzle within a 64B row
static __device__ __forceinline__ int swz(int row, int u) {
    return (u ^ row ^ (row >> 2)) & 3;
}
// sortable pack: larger value wins; tie -> smaller col wins (first occurrence)
static __device__ __forceinline__ unsigned long long pack_best(float v, int col) {
    uint32_t u = __float_as_uint(v);
    uint32_t key = (u & 0x80000000u) ? ~u : (u | 0x80000000u);
    return ((unsigned long long)key << 32) | (uint32_t)(~col);
}

// ============================================================================
// Prep: fp32 -> bf16 hi
// ============================================================================
__global__ void split_emb_kernel(const float* __restrict__ src) {
    int i = blockIdx.x * blockDim.x + threadIdx.x;
    if (i >= 4096 * 256 / 4) return;
    float4 v = ((const float4*)src)[i];
    ((__nv_bfloat162*)g_emb_hi)[2 * i + 0] =
        __nv_bfloat162(__float2bfloat16(v.x), __float2bfloat16(v.y));
    ((__nv_bfloat162*)g_emb_hi)[2 * i + 1] =
        __nv_bfloat162(__float2bfloat16(v.z), __float2bfloat16(v.w));
}
__global__ void split_q_kernel(const float* __restrict__ src) {
    int i = blockIdx.x * blockDim.x + threadIdx.x;
    if (i >= 65536 * 256 / 4) return;
    float4 v = ((const float4*)src)[i];
    ((__nv_bfloat162*)g_q_hi)[2 * i + 0] =
        __nv_bfloat162(__float2bfloat16(v.x), __float2bfloat16(v.y));
    ((__nv_bfloat162*)g_q_hi)[2 * i + 1] =
        __nv_bfloat162(__float2bfloat16(v.z), __float2bfloat16(v.w));
}

// reset per-launch state (graph-replay safe)
__global__ void init_state_kernel() {
    int i = blockIdx.x * blockDim.x + threadIdx.x;
    if (i < 4096) g_best[i] = 0ull;
    if (i == 0) g_cnt = 0;
}

// ============================================================================
// Pass 1 (unchanged from R7): hi-only sim tile-max via HMMA.
// ============================================================================
#define SM_A     0
#define SM_B     65536
#define SM_RV    (65536 + 3 * 8192)
#define SM_TOT   (SM_RV + 128 * 4 * 4)

__global__ __launch_bounds__(256)
void pass1_mma_kernel()
{
    extern __shared__ __align__(16) char smem[];
    const uint32_t sA = smem_to_u32(smem) + SM_A;
    const uint32_t sB = smem_to_u32(smem) + SM_B;
    float (*rv)[4] = (float (*)[4])(smem + SM_RV);

    const int tid  = threadIdx.x;
    const int wid  = tid >> 5;
    const int lane = tid & 31;
    const int qrow = lane >> 2;
    const int qcol = lane & 3;
    const int wm   = (wid >> 2) * 64;
    const int wn   = (wid & 3) * 32;
    const int m0   = blockIdx.x * 128;
    const int by   = blockIdx.y;

    const int T = (NTILES - by + NSPLIT - 1) / NSPLIT;
    const int G = T * 8;

#pragma unroll
    for (int i = 0; i < 16; i++) {
        const int w = i * 256 + tid;
        const int kc = w >> 9, wu = w & 511;
        const int row = wu >> 2, un = wu & 3;
        cp16(sA + kc * 8192 + row * 64 + (swz(row, un) << 4),
             g_emb_hi + (((size_t)(m0 + row)) << 8) + kc * 32 + un * 8);
    }
    CP_COMMIT();

#pragma unroll
    for (int g0 = 0; g0 < 2; g0++) {
        const int t = g0 >> 3, kc = g0 & 7;
        const int n0 = (by + t * NSPLIT) * 128;
#pragma unroll
        for (int v = 0; v < 2; v++) {
            const int u = tid * 2 + v;
            const int row = u >> 2, un = u & 3;
            cp16(sB + (g0 % 3) * 8192 + row * 64 + (swz(row, un) << 4),
                 g_q_hi + (((size_t)(n0 + row)) << 8) + kc * 32 + un * 8);
        }
        CP_COMMIT();
    }

    float acc[4][4][4];
#pragma unroll
    for (int i = 0; i < 4; i++)
#pragma unroll
        for (int j = 0; j < 4; j++)
#pragma unroll
            for (int k = 0; k < 4; k++) acc[i][j][k] = 0.f;

#pragma unroll 1
    for (int g = 0; g < G; g++) {
        __syncthreads();
        if (g + 2 < G) {
            const int gn = g + 2;
            const int t = gn >> 3, kc = gn & 7;
            const int n0 = (by + t * NSPLIT) * 128;
#pragma unroll
            for (int v = 0; v < 2; v++) {
                const int u = tid * 2 + v;
                const int row = u >> 2, un = u & 3;
                cp16(sB + (gn % 3) * 8192 + row * 64 + (swz(row, un) << 4),
                     g_q_hi + (((size_t)(n0 + row)) << 8) + kc * 32 + un * 8);
            }
            CP_COMMIT();
            CP_WAIT(2);
        } else if (g + 2 == G) {
            CP_WAIT(1);
        } else {
            CP_WAIT(0);
        }
        __syncthreads();

        const int kc = g & 7;
        const uint32_t sAb = sA + (uint32_t)(kc * 8192);
        const uint32_t sBb = sB + (uint32_t)((g % 3) * 8192);

#pragma unroll
        for (int s = 0; s < 2; s++) {
            const int u0 = 2 * s, u1 = 2 * s + 1;
            uint32_t bf[4][2];
#pragma unroll
            for (int j = 0; j < 4; j++) {
                const int n = wn + j * 8 + qrow;
                bf[j][0] = lds32(sBb + n * 64 + (swz(n, u0) << 4) + qcol * 4);
                bf[j][1] = lds32(sBb + n * 64 + (swz(n, u1) << 4) + qcol * 4);
            }
#pragma unroll
            for (int i = 0; i < 4; i++) {
                const int r0 = wm + i * 16 + qrow;
                const int r1 = r0 + 8;
                uint32_t af[4];
                af[0] = lds32(sAb + r0 * 64 + (swz(r0, u0) << 4) + qcol * 4);
                af[1] = lds32(sAb + r1 * 64 + (swz(r1, u0) << 4) + qcol * 4);
                af[2] = lds32(sAb + r0 * 64 + (swz(r0, u1) << 4) + qcol * 4);
                af[3] = lds32(sAb + r1 * 64 + (swz(r1, u1) << 4) + qcol * 4);
#pragma unroll
                for (int j = 0; j < 4; j++)
                    mma_bf16(acc[i][j], af, bf[j]);
            }
        }

        if (kc == 7) {
            const int tile_c = by + (g >> 3) * NSPLIT;
#pragma unroll
            for (int i = 0; i < 4; i++) {
#pragma unroll
                for (int rh = 0; rh < 2; rh++) {
                    float bv = -INFINITY;
#pragma unroll
                    for (int j = 0; j < 4; j++) {
                        bv = fmaxf(bv, acc[i][j][rh * 2 + 0]);
                        bv = fmaxf(bv, acc[i][j][rh * 2 + 1]);
                    }
                    bv = fmaxf(bv, __shfl_xor_sync(0xffffffffu, bv, 1));
                    bv = fmaxf(bv, __shfl_xor_sync(0xffffffffu, bv, 2));
                    if (qcol == 0)
                        rv[wm + i * 16 + rh * 8 + qrow][wid & 3] = bv;
                }
            }
            __syncthreads();
            if (tid < 128) {
                float bv = fmaxf(fmaxf(rv[tid][0], rv[tid][1]),
                                 fmaxf(rv[tid][2], rv[tid][3]));
                g_tmax[(size_t)(m0 + tid) * NTILES + tile_c] = bv;
            }
#pragma unroll
            for (int i = 0; i < 4; i++)
#pragma unroll
                for (int j = 0; j < 4; j++)
#pragma unroll
                    for (int k = 0; k < 4; k++) acc[i][j][k] = 0.f;
        }
    }
}

// ============================================================================
// Scan: per row compute measured margin and emit candidate (row,tile) pairs.
// margin = ||a - a_hi|| + 2^-9*1.01*||a_hi||  (b-side: ||db||<=2^-9, ||b||=1)
// thr = M_hi - 2*margin*1.05 - 1e-3
// ============================================================================
__global__ __launch_bounds__(256)
void scan_kernel(const float* __restrict__ emb)
{
    __shared__ float tmax_s[NTILES];
    __shared__ float red[16];

    const int r   = blockIdx.x;
    const int tid = threadIdx.x;

    const float a  = emb[(size_t)r * 256 + tid];
    const float ah = __bfloat162float(g_emb_hi[(size_t)r * 256 + tid]);
    const float dd = a - ah;
    tmax_s[tid]       = g_tmax[(size_t)r * NTILES + tid];
    tmax_s[tid + 256] = g_tmax[(size_t)r * NTILES + tid + 256];

    float p1 = dd * dd;
    float p2 = ah * ah;
    float m  = fmaxf(tmax_s[tid], tmax_s[tid + 256]);
#pragma unroll
    for (int o = 16; o; o >>= 1) {
        p1 += __shfl_xor_sync(0xffffffffu, p1, o);
        p2 += __shfl_xor_sync(0xffffffffu, p2, o);
        m = fmaxf(m, __shfl_xor_sync(0xffffffffu, m, o));
    }
    if ((tid & 31) == 0) {
        red[tid >> 5] = p1; red[(tid >> 5) + 8] = p2;
    }
    __syncthreads();
    __shared__ float s_thr;
    if (tid < 32) {
        // warp 0 lane w also needs the max: use smem for maxes via reuse
    }
    __shared__ float redm[8];
    if ((tid & 31) == 0) redm[tid >> 5] = m;
    __syncthreads();
    if (tid == 0) {
        float s1 = 0.f, s2 = 0.f, mm = -INFINITY;
#pragma unroll
        for (int w = 0; w < 8; w++) {
            s1 += red[w]; s2 += red[w + 8]; mm = fmaxf(mm, redm[w]);
        }
        const float margin = sqrtf(s1) + 0.002f * sqrtf(s2);
        s_thr = mm - 2.1f * margin - 1e-3f;
    }
    __syncthreads();
    const float thr = s_thr;

#pragma unroll
    for (int h = 0; h < 2; h++) {
        const int t = tid + h * 256;
        if (tmax_s[t] >= thr) {
            const int idx = atomicAdd(&g_cnt, 1);
            if (idx < WL_CAP) g_wl[idx] = ((uint32_t)r << 9) | (uint32_t)t;
        }
    }
}

// ============================================================================
// Candidate dots: warp-per-column, lane-split-k (coalesced), fp32 exact,
// order-independent atomicMax merge into g_best[row].
// ============================================================================
__global__ __launch_bounds__(256)
void cand_dot_kernel(const float* __restrict__ emb,
                     const float* __restrict__ queue)
{
    __shared__ float arow[256];
    __shared__ unsigned long long wbest[8];

    const int tid  = threadIdx.x;
    const int wid  = tid >> 5;
    const int lane = tid & 31;
    const int cnt  = min(g_cnt, WL_CAP);

    for (int e = blockIdx.x; e < cnt; e += gridDim.x) {
        const uint32_t ent = g_wl[e];
        const int r    = (int)(ent >> 9);
        const int tile = (int)(ent & 511u);

        __syncthreads();                  // retire previous iter's arow readers
        arow[tid] = emb[(size_t)r * 256 + tid];
        __syncthreads();

        const int k0 = lane * 8;
        const float4 a0 = *(const float4*)&arow[k0];
        const float4 a1 = *(const float4*)&arow[k0 + 4];

        float bv = -INFINITY;
        int   bi = 0x7fffffff;
#pragma unroll 4
        for (int c = wid; c < 128; c += 8) {
            const int col = tile * 128 + c;
            const float4* qp = (const float4*)(queue + (size_t)col * 256 + k0);
            const float4 q0 = qp[0];
            const float4 q1 = qp[1];
            float s = a0.x * q0.x;
            s = fmaf(a0.y, q0.y, s);
            s = fmaf(a0.z, q0.z, s);
            s = fmaf(a0.w, q0.w, s);
            s = fmaf(a1.x, q1.x, s);
            s = fmaf(a1.y, q1.y, s);
            s = fmaf(a1.z, q1.z, s);
            s = fmaf(a1.w, q1.w, s);
#pragma unroll
            for (int o = 16; o; o >>= 1)
                s += __shfl_xor_sync(0xffffffffu, s, o);
            // cols ascend within this warp's sequence -> strict > keeps first
            if (s > bv) { bv = s; bi = col; }
        }
        if (lane == 0) wbest[wid] = pack_best(bv, bi);
        __syncthreads();
        if (tid == 0) {
            unsigned long long mb = wbest[0];
#pragma unroll
            for (int w = 1; w < 8; w++) mb = mb < wbest[w] ? wbest[w] : mb;
            atomicMax(&g_best[r], mb);
        }
    }
}

__global__ void decode_kernel()
{
    int i = blockIdx.x * blockDim.x + threadIdx.x;
    if (i < 4096) g_nn[i] = (int)(~(uint32_t)(g_best[i] & 0xffffffffu));
}

// ============================================================================
// Stage 2a: logits[s][i][j] = 10 * dot(queue[nn[s*half+i]], preds[(1-s)*half+j])
// ============================================================================
__global__ __launch_bounds__(256)
void logits_kernel(const float* __restrict__ queue, const float* __restrict__ preds,
                   int half)
{
    __shared__ int   idx_s[BM2];
    __shared__ float As[BK2][BM2 + 4];
    __shared__ float Bs[BK2][BN2 + 4];

    const int tid = threadIdx.x;
    const int tx = tid & 15;
    const int ty = tid >> 4;
    const int s  = blockIdx.z;
    const int m0 = blockIdx.x * BM2;
    const int n0 = blockIdx.y * BN2;

    if (tid < BM2) idx_s[tid] = g_nn[s * half + m0 + tid];
    __syncthreads();

    const float* pb = preds + (size_t)(1 - s) * half * D;
    const int lm  = tid >> 2;
    const int lk4 = (tid & 3) * 4;

    float acc[4][4] = {};

    for (int k0 = 0; k0 < D; k0 += BK2) {
        float4 av = *(const float4*)&queue[(size_t)idx_s[lm] * D + k0 + lk4];
        float4 bv = *(const float4*)&pb[(size_t)(n0 + lm) * D + k0 + lk4];
        __syncthreads();
        As[lk4 + 0][lm] = av.x; As[lk4 + 1][lm] = av.y;
        As[lk4 + 2][lm] = av.z; As[lk4 + 3][lm] = av.w;
        Bs[lk4 + 0][lm] = bv.x; Bs[lk4 + 1][lm] = bv.y;
        Bs[lk4 + 2][lm] = bv.z; Bs[lk4 + 3][lm] = bv.w;
        __syncthreads();
#pragma unroll
        for (int k = 0; k < BK2; k++) {
            float4 a = *(const float4*)&As[k][ty * 4];
            float4 b = *(const float4*)&Bs[k][tx * 4];
            float am[4] = {a.x, a.y, a.z, a.w};
            float bn[4] = {b.x, b.y, b.z, b.w};
#pragma unroll
            for (int i = 0; i < 4; i++)
#pragma unroll
                for (int j = 0; j < 4; j++)
                    acc[i][j] += am[i] * bn[j];
        }
    }

#pragma unroll
    for (int i = 0; i < 4; i++) {
        const int row = s * half + m0 + ty * 4 + i;
        float4 o = make_float4(acc[i][0] * 10.f, acc[i][1] * 10.f,
                               acc[i][2] * 10.f, acc[i][3] * 10.f);
        *(float4*)&g_logits[(size_t)row * half + n0 + tx * 4] = o;
    }
}

// ============================================================================
// Stage 2b: per-row logsumexp(row) - row[diag]
// ============================================================================
__global__ __launch_bounds__(256)
void ce_row_kernel(int half)
{
    __shared__ float red[8];
    const int row = blockIdx.x;
    const int tid = threadIdx.x;
    const float* L = g_logits + (size_t)row * half;

    float m = -INFINITY;
    for (int j = tid; j < half; j += 256) m = fmaxf(m, L[j]);
#pragma unroll
    for (int o = 16; o; o >>= 1) m = fmaxf(m, __shfl_xor_sync(0xffffffffu, m, o));
    if ((tid & 31) == 0) red[tid >> 5] = m;
    __syncthreads();
    if (tid == 0) {
        float tt = red[0];
#pragma unroll
        for (int w = 1; w < 8; w++) tt = fmaxf(tt, red[w]);
        red[0] = tt;
    }
    __syncthreads();
    const float bm = red[0];
    __syncthreads();

    float sum = 0.f;
    for (int j = tid; j < half; j += 256) sum += expf(L[j] - bm);
#pragma unroll
    for (int o = 16; o; o >>= 1) sum += __shfl_xor_sync(0xffffffffu, sum, o);
    if ((tid & 31) == 0) red[tid >> 5] = sum;
    __syncthreads();
    if (tid == 0) {
        float tt = 0.f;
#pragma unroll
        for (int w = 0; w < 8; w++) tt += red[w];
        int diag = row % half;
        g_rowterm[row] = logf(tt) + bm - L[diag];
    }
}

__global__ __launch_bounds__(256)
void final_kernel(float* __restrict__ out, int total)
{
    __shared__ float red[8];
    const int tid = threadIdx.x;
    float s = 0.f;
    for (int i = tid; i < total; i += 256) s += g_rowterm[i];
#pragma unroll
    for (int o = 16; o; o >>= 1) s += __shfl_xor_sync(0xffffffffu, s, o);
    if ((tid & 31) == 0) red[tid >> 5] = s;
    __syncthreads();
    if (tid == 0) {
        float tt = 0.f;
#pragma unroll
        for (int w = 0; w < 8; w++) tt += red[w];
        out[0] = tt / (float)total;
    }
}

// ============================================================================
extern "C" void kernel_launch(void* const* d_in, const int* in_sizes, int n_in,
                              void* d_out, int out_size)
{
    const float* emb   = (const float*)d_in[0];   // [4096, 256]
    const float* preds = (const float*)d_in[1];   // [4096, 256]
    const float* queue = (const float*)d_in[2];   // [65536, 256]

    const int B = in_sizes[0] / D;     // 4096
    const int half = B / 2;            // 2048

    cudaFuncSetAttribute(pass1_mma_kernel,
                         cudaFuncAttributeMaxDynamicSharedMemorySize, SM_TOT);

    split_emb_kernel<<<(4096 * 256 / 4 + 255) / 256, 256>>>(emb);
    split_q_kernel<<<(65536 * 256 / 4 + 255) / 256, 256>>>(queue);
    init_state_kernel<<<16, 256>>>();
    pass1_mma_kernel<<<dim3(B / 128, NSPLIT), 256, SM_TOT>>>();
    scan_kernel<<<B, 256>>>(emb);
    cand_dot_kernel<<<4096, 256>>>(emb, queue);
    decode_kernel<<<16, 256>>>();
    logits_kernel<<<dim3(half / BM2, half / BN2, 2), 256>>>(queue, preds, half);
    ce_row_kernel<<<2 * half, 256>>>(half);
    final_kernel<<<1, 256>>>((float*)d_out, 2 * half);
}